// round 16
// baseline (speedup 1.0000x reference)
#include <cuda_runtime.h>

#define RR 256
#define CC 32
#define SS 8
#define HH 32
#define WARPS 8
#define NT (WARPS*32)
#define FSTR 36
#define WSTR 36

#define NBQ 64                     // bins per axis (locality optimum)
#define NBINS (NBQ*NBQ*NBQ)        // 262144
#define SCAN_BLKS (NBINS/1024)     // 256
#define MAXN 2097152

__constant__ float cWOUT[HH], cCWOUT[HH*3];
__constant__ float cBND[SS*6];
__constant__ float cBO[1], cCBO[3];

__device__ int g_bins[NBINS];
__device__ int g_cursor[NBINS];
__device__ int g_bsum[SCAN_BLKS];
__device__ float4 g_psort[MAXN];

// ---------------- sorting kernels ----------------
__device__ __forceinline__ int bin_key(float px, float py, float pz) {
    int qx = (int)(px * (float)NBQ); qx = max(0, min(NBQ - 1, qx));
    int qy = (int)(py * (float)NBQ); qy = max(0, min(NBQ - 1, qy));
    int qz = (int)(pz * (float)NBQ); qz = max(0, min(NBQ - 1, qz));
    return (qx << 12) | (qy << 6) | qz;
}

__global__ void zero_bins_kernel() {
    int i = blockIdx.x * blockDim.x + threadIdx.x;
    if (i < NBINS) g_bins[i] = 0;
}

__global__ void hist_kernel(const float* __restrict__ p, int n) {
    int i = blockIdx.x * blockDim.x + threadIdx.x;
    if (i >= n) return;
    atomicAdd(&g_bins[bin_key(p[i*3], p[i*3+1], p[i*3+2])], 1);
}

__global__ __launch_bounds__(1024) void scan_a_kernel() {
    __shared__ int sh[1024];
    const int t = threadIdx.x;
    const int i = blockIdx.x * 1024 + t;
    const int v = g_bins[i];
    sh[t] = v;
    __syncthreads();
    for (int off = 1; off < 1024; off <<= 1) {
        int u = (t >= off) ? sh[t - off] : 0;
        __syncthreads();
        sh[t] += u;
        __syncthreads();
    }
    g_cursor[i] = sh[t] - v;
    if (t == 1023) g_bsum[blockIdx.x] = sh[t];
}

__global__ __launch_bounds__(SCAN_BLKS) void scan_b_kernel() {
    __shared__ int sh[SCAN_BLKS];
    const int t = threadIdx.x;
    const int v = g_bsum[t];
    sh[t] = v;
    __syncthreads();
    for (int off = 1; off < SCAN_BLKS; off <<= 1) {
        int u = (t >= off) ? sh[t - off] : 0;
        __syncthreads();
        sh[t] += u;
        __syncthreads();
    }
    g_bsum[t] = sh[t] - v;
}

__global__ void scatter_kernel(const float* __restrict__ p, int n) {
    int i = blockIdx.x * blockDim.x + threadIdx.x;
    if (i >= n) return;
    const float px = p[i*3], py = p[i*3+1], pz = p[i*3+2];
    const int key = bin_key(px, py, pz);
    int pos = atomicAdd(&g_cursor[key], 1) + g_bsum[key >> 10];
    float4 v; v.x = px; v.y = py; v.z = pz; v.w = __int_as_float(i);
    g_psort[pos] = v;
}

// ---------------- main kernel ----------------
#define SM_W0    0
#define SM_W1    1152
#define SM_CW0   2304
#define SM_CW1   3456
#define SM_PAR   4608
#define SM_FEAT  8704
#define SM_B0    17920
#define SM_B1    17952
#define SM_CB0   17984
#define SM_CB1   18016
#define SMEM_FLOATS 18048

__device__ __forceinline__ unsigned f2tf(float f) {
    unsigned r; asm("cvt.rna.tf32.f32 %0, %1;" : "=r"(r) : "f"(f)); return r;
}
__device__ __forceinline__ void split_tf(float f, unsigned& hi, unsigned& lo) {
    hi = f2tf(f);
    lo = f2tf(f - __uint_as_float(hi));
}
__device__ __forceinline__ void mma8(float* c, const unsigned* a, unsigned b0, unsigned b1) {
    asm("mma.sync.aligned.m16n8k8.row.col.f32.tf32.tf32.f32 "
        "{%0,%1,%2,%3},{%4,%5,%6,%7},{%8,%9},{%0,%1,%2,%3};"
        : "+f"(c[0]), "+f"(c[1]), "+f"(c[2]), "+f"(c[3])
        : "r"(a[0]), "r"(a[1]), "r"(a[2]), "r"(a[3]), "r"(b0), "r"(b1));
}

__device__ __forceinline__ void gemm_layer(const float* __restrict__ sf,
                                           const float* __restrict__ W,
                                           const float* __restrict__ Bias,
                                           float c[2][4][4], int lane)
{
    const int qr = lane >> 2;
    const int qc = lane & 3;
    #pragma unroll
    for (int nn = 0; nn < 4; nn++) {
        const float2 bv = *(const float2*)&Bias[nn*8 + 2*qc];
        #pragma unroll
        for (int mt = 0; mt < 2; mt++) {
            c[mt][nn][0] = bv.x; c[mt][nn][1] = bv.y;
            c[mt][nn][2] = bv.x; c[mt][nn][3] = bv.y;
        }
    }
    #pragma unroll
    for (int kk = 0; kk < 4; kk++) {
        unsigned ah[2][4], al[2][4];
        #pragma unroll
        for (int mt = 0; mt < 2; mt++) {
            const int r0 = mt*16 + qr;
            const int ch = kk*8 + qc;
            split_tf(sf[r0*FSTR + ch],          ah[mt][0], al[mt][0]);
            split_tf(sf[(r0+8)*FSTR + ch],      ah[mt][1], al[mt][1]);
            split_tf(sf[r0*FSTR + ch + 4],      ah[mt][2], al[mt][2]);
            split_tf(sf[(r0+8)*FSTR + ch + 4],  ah[mt][3], al[mt][3]);
        }
        #pragma unroll
        for (int nn = 0; nn < 4; nn++) {
            const int kr = kk*8 + qc;
            const int ncol = nn*8 + qr;
            const float w0 = W[kr*WSTR + ncol];
            const float w1 = W[(kr+4)*WSTR + ncol];
            unsigned bh0, bl0, bh1, bl1;
            split_tf(w0, bh0, bl0);
            split_tf(w1, bh1, bl1);
            #pragma unroll
            for (int mt = 0; mt < 2; mt++) {
                mma8(c[mt][nn], ah[mt], bh0, bh1);
                mma8(c[mt][nn], al[mt], bh0, bh1);
                mma8(c[mt][nn], ah[mt], bl0, bl1);
            }
        }
    }
}

__device__ __forceinline__ void relu_store_c(float* __restrict__ sf,
                                             const float c[2][4][4], int lane)
{
    const int qr = lane >> 2, qc = lane & 3;
    #pragma unroll
    for (int mt = 0; mt < 2; mt++) {
        #pragma unroll
        for (int nn = 0; nn < 4; nn++) {
            const int pt = mt*16 + qr;
            const int j  = nn*8 + 2*qc;
            float2 v0, v1;
            v0.x = fmaxf(c[mt][nn][0], 0.0f); v0.y = fmaxf(c[mt][nn][1], 0.0f);
            v1.x = fmaxf(c[mt][nn][2], 0.0f); v1.y = fmaxf(c[mt][nn][3], 0.0f);
            *(float2*)&sf[pt*FSTR + j]     = v0;
            *(float2*)&sf[(pt+8)*FSTR + j] = v1;
        }
    }
}

// run-compressed warp-cooperative gather: offsets are warp-shared (from par),
// so the "same cell as previous point" test is warp-uniform. Corner values are
// kept in registers across a run and only reloaded at run boundaries.
__device__ __forceinline__ void gather32(
    const float* __restrict__ P0, const float* __restrict__ P1, const float* __restrict__ P2,
    const float* __restrict__ par, float* __restrict__ sfeat, int lane)
{
    float a0=0, a1=0, a2=0, a3=0, b0=0, b1=0, b2=0, b3=0, c0=0, c1=0, c2=0, c3=0;
    int prevx = -1, prevy = -1, prevz = -1;
    #pragma unroll 1
    for (int pt = 0; pt < 32; pt++) {
        const int4 qo = *(const int4*)&par[pt * 16 + 12];
        if ((qo.x != prevx) | (qo.y != prevy) | (qo.z != prevz)) {
            const float* a = P0 + qo.x + lane;
            const float* b = P1 + qo.y + lane;
            const float* c = P2 + qo.z + lane;
            a0 = a[0]; a1 = a[CC]; a2 = a[RR*CC]; a3 = a[RR*CC + CC];
            b0 = b[0]; b1 = b[CC]; b2 = b[RR*CC]; b3 = b[RR*CC + CC];
            c0 = c[0]; c1 = c[CC]; c2 = c[RR*CC]; c3 = c[RR*CC + CC];
            prevx = qo.x; prevy = qo.y; prevz = qo.z;
        }
        const float4 q0 = *(const float4*)&par[pt * 16 + 0];
        const float4 q1 = *(const float4*)&par[pt * 16 + 4];
        const float4 q2 = *(const float4*)&par[pt * 16 + 8];
        float f;
        f  = q0.x * a0 + q0.y * a1 + q0.z * a2 + q0.w * a3;
        f += q1.x * b0 + q1.y * b1 + q1.z * b2 + q1.w * b3;
        f += q2.x * c0 + q2.y * c1 + q2.z * c2 + q2.w * c3;
        sfeat[pt * FSTR + lane] = f;
    }
}

__global__ __launch_bounds__(NT, 3) void decoders_kernel(
    const float* __restrict__ pxy, const float* __restrict__ pxz, const float* __restrict__ pyz,
    const float* __restrict__ cxy, const float* __restrict__ cxz, const float* __restrict__ cyz,
    const float* __restrict__ w0, const float* __restrict__ w1,
    const float* __restrict__ cw0, const float* __restrict__ cw1,
    const float* __restrict__ b0, const float* __restrict__ b1,
    const float* __restrict__ cb0, const float* __restrict__ cb1,
    float* __restrict__ out, int n)
{
    extern __shared__ float smem[];
    const int tid = threadIdx.x;

    for (int i = tid; i < CC * HH; i += NT) {
        const int r = i >> 5, c = i & 31;
        smem[SM_W0  + r*WSTR + c] = w0[i];
        smem[SM_W1  + r*WSTR + c] = w1[i];
        smem[SM_CW0 + r*WSTR + c] = cw0[i];
        smem[SM_CW1 + r*WSTR + c] = cw1[i];
    }
    if (tid < HH) {
        smem[SM_B0  + tid] = b0[tid];
        smem[SM_B1  + tid] = b1[tid];
        smem[SM_CB0 + tid] = cb0[tid];
        smem[SM_CB1 + tid] = cb1[tid];
    }

    const int warp = tid >> 5, lane = tid & 31;
    const int base = (blockIdx.x * WARPS + warp) * 32;
    float* __restrict__ par   = smem + SM_PAR  + warp * (32 * 16);
    float* __restrict__ sfeat = smem + SM_FEAT + warp * (32 * FSTR);

    int pi = -1;
    {
        const int idx = base + lane;
        float px = 2.0f, py = 2.0f, pz = 2.0f;
        if (idx < n) {
            const float4 ps = g_psort[idx];
            px = ps.x; py = ps.y; pz = ps.z;
            pi = __float_as_int(ps.w);
        }

        int s = 0; bool valid = false;
        #pragma unroll
        for (int k = SS - 1; k >= 0; k--) {
            const float lx = cBND[k*6+0], ly = cBND[k*6+1], lz = cBND[k*6+2];
            const float hx = cBND[k*6+3], hy = cBND[k*6+4], hz = cBND[k*6+5];
            const bool in = (px > lx) & (px < hx) & (py > ly) & (py < hy) & (pz > lz) & (pz < hz);
            if (in) { s = k; valid = true; }
        }
        const float m = valid ? 1.0f : 0.0f;

        const float bx0 = cBND[s*6+0], by0 = cBND[s*6+1], bz0 = cBND[s*6+2];
        const float bx1 = cBND[s*6+3], by1 = cBND[s*6+4], bz1 = cBND[s*6+5];
        const float pnx = (px - bx0) / (bx1 - bx0) * 2.0f - 1.0f;
        const float pny = (py - by0) / (by1 - by0) * 2.0f - 1.0f;
        const float pnz = (pz - bz0) / (bz1 - bz0) * 2.0f - 1.0f;

        const float us[3] = { pnx, pnx, pny };
        const float vs[3] = { pny, pnz, pnz };
        #pragma unroll
        for (int t = 0; t < 3; t++) {
            const float x = (us[t] + 1.0f) * 0.5f * (float)(RR - 1);
            const float y = (vs[t] + 1.0f) * 0.5f * (float)(RR - 1);
            const float xf = fminf(fmaxf(floorf(x), 0.0f), (float)(RR - 2));
            const float yf = fminf(fmaxf(floorf(y), 0.0f), (float)(RR - 2));
            const float wx = x - xf, wy = y - yf;
            float4 q;
            q.x = m * (1.0f - wx) * (1.0f - wy);
            q.y = m * wx * (1.0f - wy);
            q.z = m * (1.0f - wx) * wy;
            q.w = m * wx * wy;
            *(float4*)&par[lane * 16 + t * 4] = q;
            ((int*)par)[lane * 16 + 12 + t] = ((s * RR + (int)yf) * RR + (int)xf) * CC;
        }
    }
    __syncthreads();

    float c[2][4][4];

    // ================= SDF branch =================
    gather32(pxy, pxz, pyz, par, sfeat, lane);
    __syncwarp();
    gemm_layer(sfeat, smem + SM_W0, smem + SM_B0, c, lane);
    __syncwarp();
    relu_store_c(sfeat, c, lane);
    __syncwarp();
    gemm_layer(sfeat, smem + SM_W1, smem + SM_B1, c, lane);
    __syncwarp();
    relu_store_c(sfeat, c, lane);
    __syncwarp();

    float sdf;
    {
        const float* row = sfeat + lane * FSTR;
        float acc = cBO[0];
        #pragma unroll
        for (int j4 = 0; j4 < 8; j4++) {
            const float4 v = *(const float4*)&row[j4 * 4];
            acc += v.x * cWOUT[j4*4+0] + v.y * cWOUT[j4*4+1]
                 + v.z * cWOUT[j4*4+2] + v.w * cWOUT[j4*4+3];
        }
        sdf = tanhf(acc);
    }
    __syncwarp();

    // ================= Color branch =================
    gather32(cxy, cxz, cyz, par, sfeat, lane);
    __syncwarp();
    gemm_layer(sfeat, smem + SM_CW0, smem + SM_CB0, c, lane);
    __syncwarp();
    relu_store_c(sfeat, c, lane);
    __syncwarp();
    gemm_layer(sfeat, smem + SM_CW1, smem + SM_CB1, c, lane);
    __syncwarp();
    relu_store_c(sfeat, c, lane);
    __syncwarp();

    float rA = cCBO[0], gA = cCBO[1], bA = cCBO[2];
    {
        const float* row = sfeat + lane * FSTR;
        #pragma unroll
        for (int j = 0; j < HH; j++) {
            const float hv = row[j];
            rA += hv * cCWOUT[j*3 + 0];
            gA += hv * cCWOUT[j*3 + 1];
            bA += hv * cCWOUT[j*3 + 2];
        }
    }

    if (pi >= 0) {
        float4 o;
        o.x = 1.0f / (1.0f + expf(-rA));
        o.y = 1.0f / (1.0f + expf(-gA));
        o.z = 1.0f / (1.0f + expf(-bA));
        o.w = sdf;
        ((float4*)out)[pi] = o;
    }
}

extern "C" void kernel_launch(void* const* d_in, const int* in_sizes, int n_in,
                              void* d_out, int out_size) {
    const float* p          = (const float*)d_in[0];
    const float* boundaries = (const float*)d_in[1];
    const float* pxy        = (const float*)d_in[2];
    const float* pxz        = (const float*)d_in[3];
    const float* pyz        = (const float*)d_in[4];
    const float* cxy        = (const float*)d_in[5];
    const float* cxz        = (const float*)d_in[6];
    const float* cyz        = (const float*)d_in[7];
    const float* w0         = (const float*)d_in[8];
    const float* b0         = (const float*)d_in[9];
    const float* w1         = (const float*)d_in[10];
    const float* b1         = (const float*)d_in[11];
    const float* cw0        = (const float*)d_in[14];
    const float* cb0        = (const float*)d_in[15];
    const float* cw1        = (const float*)d_in[16];
    const float* cb1        = (const float*)d_in[17];

    cudaMemcpyToSymbolAsync(cWOUT,  d_in[12], HH*4,   0, cudaMemcpyDeviceToDevice, 0);
    cudaMemcpyToSymbolAsync(cBO,    d_in[13], 4,      0, cudaMemcpyDeviceToDevice, 0);
    cudaMemcpyToSymbolAsync(cCWOUT, d_in[18], HH*3*4, 0, cudaMemcpyDeviceToDevice, 0);
    cudaMemcpyToSymbolAsync(cCBO,   d_in[19], 3*4,    0, cudaMemcpyDeviceToDevice, 0);
    cudaMemcpyToSymbolAsync(cBND,   boundaries, SS*6*4, 0, cudaMemcpyDeviceToDevice, 0);

    const int n = in_sizes[0] / 3;
    float* out = (float*)d_out;

    zero_bins_kernel<<<(NBINS + 255) / 256, 256>>>();
    hist_kernel<<<(n + 255) / 256, 256>>>(p, n);
    scan_a_kernel<<<SCAN_BLKS, 1024>>>();
    scan_b_kernel<<<1, SCAN_BLKS>>>();
    scatter_kernel<<<(n + 255) / 256, 256>>>(p, n);

    const int smem_bytes = SMEM_FLOATS * (int)sizeof(float);
    cudaFuncSetAttribute(decoders_kernel,
                         cudaFuncAttributeMaxDynamicSharedMemorySize, smem_bytes);

    const int pts_per_block = NT;   // 256
    const int blocks = (n + pts_per_block - 1) / pts_per_block;
    decoders_kernel<<<blocks, NT, smem_bytes>>>(
        pxy, pxz, pyz, cxy, cxz, cyz,
        w0, w1, cw0, cw1, b0, b1, cb0, cb1, out, n);
}

// round 17
// speedup vs baseline: 1.0283x; 1.0283x over previous
#include <cuda_runtime.h>

#define RR 256
#define CC 32
#define SS 8
#define HH 32
#define WARPS 8
#define NT (WARPS*32)
#define FSTR 36
#define WSTR 36

#define NBQ 64                     // bins per axis (locality optimum)
#define NBINS (NBQ*NBQ*NBQ)        // 262144
#define SCAN_BLKS (NBINS/1024)     // 256
#define MAXN 2097152

__constant__ float cWOUT[HH], cCWOUT[HH*3];
__constant__ float cBND[SS*6];
__constant__ float cBO[1], cCBO[3];

__device__ int g_bins[NBINS];      // zero-initialized (BSS); scatter re-zeroes for next replay
__device__ int g_cursor[NBINS];
__device__ int g_bsum[SCAN_BLKS];
__device__ float4 g_psort[MAXN];

// ---------------- sorting kernels ----------------
// x-major key: consecutive bins sweep qz fastest -> long runs share the same
// xy-plane cell (best L2/L1 reuse for the dominant plane gathers)
__device__ __forceinline__ int bin_key(float px, float py, float pz) {
    int qx = (int)(px * (float)NBQ); qx = max(0, min(NBQ - 1, qx));
    int qy = (int)(py * (float)NBQ); qy = max(0, min(NBQ - 1, qy));
    int qz = (int)(pz * (float)NBQ); qz = max(0, min(NBQ - 1, qz));
    return (qx << 12) | (qy << 6) | qz;
}

__global__ void hist_kernel(const float* __restrict__ p, int n) {
    int i = blockIdx.x * blockDim.x + threadIdx.x;
    if (i >= n) return;
    atomicAdd(&g_bins[bin_key(p[i*3], p[i*3+1], p[i*3+2])], 1);
}

__global__ __launch_bounds__(1024) void scan_a_kernel() {
    __shared__ int sh[1024];
    const int t = threadIdx.x;
    const int i = blockIdx.x * 1024 + t;
    const int v = g_bins[i];
    sh[t] = v;
    __syncthreads();
    for (int off = 1; off < 1024; off <<= 1) {
        int u = (t >= off) ? sh[t - off] : 0;
        __syncthreads();
        sh[t] += u;
        __syncthreads();
    }
    g_cursor[i] = sh[t] - v;          // exclusive within block
    if (t == 1023) g_bsum[blockIdx.x] = sh[t];
}

__global__ __launch_bounds__(SCAN_BLKS) void scan_b_kernel() {
    __shared__ int sh[SCAN_BLKS];
    const int t = threadIdx.x;
    const int v = g_bsum[t];
    sh[t] = v;
    __syncthreads();
    for (int off = 1; off < SCAN_BLKS; off <<= 1) {
        int u = (t >= off) ? sh[t - off] : 0;
        __syncthreads();
        sh[t] += u;
        __syncthreads();
    }
    g_bsum[t] = sh[t] - v;            // exclusive across blocks
}

// scatter + self-clean: bins were consumed by scan_a; zero them here so the
// next graph replay (which re-runs this whole chain) starts from bins==0.
__global__ void scatter_kernel(const float* __restrict__ p, int n) {
    int i = blockIdx.x * blockDim.x + threadIdx.x;
    if (i < NBINS) g_bins[i] = 0;
    if (i >= n) return;
    const float px = p[i*3], py = p[i*3+1], pz = p[i*3+2];
    const int key = bin_key(px, py, pz);
    int pos = atomicAdd(&g_cursor[key], 1) + g_bsum[key >> 10];
    float4 v; v.x = px; v.y = py; v.z = pz; v.w = __int_as_float(i);
    g_psort[pos] = v;
}

// ---------------- main kernel ----------------
// shared memory layout (float words)
#define SM_W0    0
#define SM_W1    1152
#define SM_CW0   2304
#define SM_CW1   3456
#define SM_PAR   4608
#define SM_FEAT  8704
#define SM_B0    17920
#define SM_B1    17952
#define SM_CB0   17984
#define SM_CB1   18016
#define SMEM_FLOATS 18048

__device__ __forceinline__ unsigned f2tf(float f) {
    unsigned r; asm("cvt.rna.tf32.f32 %0, %1;" : "=r"(r) : "f"(f)); return r;
}
__device__ __forceinline__ void split_tf(float f, unsigned& hi, unsigned& lo) {
    hi = f2tf(f);
    lo = f2tf(f - __uint_as_float(hi));
}
__device__ __forceinline__ void mma8(float* c, const unsigned* a, unsigned b0, unsigned b1) {
    asm("mma.sync.aligned.m16n8k8.row.col.f32.tf32.tf32.f32 "
        "{%0,%1,%2,%3},{%4,%5,%6,%7},{%8,%9},{%0,%1,%2,%3};"
        : "+f"(c[0]), "+f"(c[1]), "+f"(c[2]), "+f"(c[3])
        : "r"(a[0]), "r"(a[1]), "r"(a[2]), "r"(a[3]), "r"(b0), "r"(b1));
}

__device__ __forceinline__ void gemm_layer(const float* __restrict__ sf,
                                           const float* __restrict__ W,
                                           const float* __restrict__ Bias,
                                           float c[2][4][4], int lane)
{
    const int qr = lane >> 2;
    const int qc = lane & 3;
    #pragma unroll
    for (int nn = 0; nn < 4; nn++) {
        const float2 bv = *(const float2*)&Bias[nn*8 + 2*qc];
        #pragma unroll
        for (int mt = 0; mt < 2; mt++) {
            c[mt][nn][0] = bv.x; c[mt][nn][1] = bv.y;
            c[mt][nn][2] = bv.x; c[mt][nn][3] = bv.y;
        }
    }
    #pragma unroll
    for (int kk = 0; kk < 4; kk++) {
        unsigned ah[2][4], al[2][4];
        #pragma unroll
        for (int mt = 0; mt < 2; mt++) {
            const int r0 = mt*16 + qr;
            const int ch = kk*8 + qc;
            split_tf(sf[r0*FSTR + ch],          ah[mt][0], al[mt][0]);
            split_tf(sf[(r0+8)*FSTR + ch],      ah[mt][1], al[mt][1]);
            split_tf(sf[r0*FSTR + ch + 4],      ah[mt][2], al[mt][2]);
            split_tf(sf[(r0+8)*FSTR + ch + 4],  ah[mt][3], al[mt][3]);
        }
        #pragma unroll
        for (int nn = 0; nn < 4; nn++) {
            const int kr = kk*8 + qc;
            const int ncol = nn*8 + qr;
            const float w0 = W[kr*WSTR + ncol];
            const float w1 = W[(kr+4)*WSTR + ncol];
            unsigned bh0, bl0, bh1, bl1;
            split_tf(w0, bh0, bl0);
            split_tf(w1, bh1, bl1);
            #pragma unroll
            for (int mt = 0; mt < 2; mt++) {
                mma8(c[mt][nn], ah[mt], bh0, bh1);
                mma8(c[mt][nn], al[mt], bh0, bh1);
                mma8(c[mt][nn], ah[mt], bl0, bl1);
            }
        }
    }
}

__device__ __forceinline__ void relu_store_c(float* __restrict__ sf,
                                             const float c[2][4][4], int lane)
{
    const int qr = lane >> 2, qc = lane & 3;
    #pragma unroll
    for (int mt = 0; mt < 2; mt++) {
        #pragma unroll
        for (int nn = 0; nn < 4; nn++) {
            const int pt = mt*16 + qr;
            const int j  = nn*8 + 2*qc;
            float2 v0, v1;
            v0.x = fmaxf(c[mt][nn][0], 0.0f); v0.y = fmaxf(c[mt][nn][1], 0.0f);
            v1.x = fmaxf(c[mt][nn][2], 0.0f); v1.y = fmaxf(c[mt][nn][3], 0.0f);
            *(float2*)&sf[pt*FSTR + j]     = v0;
            *(float2*)&sf[(pt+8)*FSTR + j] = v1;
        }
    }
}

// warp-cooperative gather: lane = channel; corner weights precomputed in par
__device__ __forceinline__ void gather32(
    const float* __restrict__ P0, const float* __restrict__ P1, const float* __restrict__ P2,
    const float* __restrict__ par, float* __restrict__ sfeat, int lane)
{
    #pragma unroll 4
    for (int pt = 0; pt < 32; pt++) {
        const float4 q0 = *(const float4*)&par[pt * 16 + 0];
        const float4 q1 = *(const float4*)&par[pt * 16 + 4];
        const float4 q2 = *(const float4*)&par[pt * 16 + 8];
        const int4   qo = *(const int4*)  &par[pt * 16 + 12];
        const float* a = P0 + qo.x + lane;
        const float* b = P1 + qo.y + lane;
        const float* c = P2 + qo.z + lane;
        float f;
        f  = q0.x * a[0] + q0.y * a[CC] + q0.z * a[RR*CC] + q0.w * a[RR*CC + CC];
        f += q1.x * b[0] + q1.y * b[CC] + q1.z * b[RR*CC] + q1.w * b[RR*CC + CC];
        f += q2.x * c[0] + q2.y * c[CC] + q2.z * c[RR*CC] + q2.w * c[RR*CC + CC];
        sfeat[pt * FSTR + lane] = f;
    }
}

__global__ __launch_bounds__(NT, 3) void decoders_kernel(
    const float* __restrict__ pxy, const float* __restrict__ pxz, const float* __restrict__ pyz,
    const float* __restrict__ cxy, const float* __restrict__ cxz, const float* __restrict__ cyz,
    const float* __restrict__ w0, const float* __restrict__ w1,
    const float* __restrict__ cw0, const float* __restrict__ cw1,
    const float* __restrict__ b0, const float* __restrict__ b1,
    const float* __restrict__ cb0, const float* __restrict__ cb1,
    float* __restrict__ out, int n)
{
    extern __shared__ float smem[];
    const int tid = threadIdx.x;

    for (int i = tid; i < CC * HH; i += NT) {
        const int r = i >> 5, c = i & 31;
        smem[SM_W0  + r*WSTR + c] = w0[i];
        smem[SM_W1  + r*WSTR + c] = w1[i];
        smem[SM_CW0 + r*WSTR + c] = cw0[i];
        smem[SM_CW1 + r*WSTR + c] = cw1[i];
    }
    if (tid < HH) {
        smem[SM_B0  + tid] = b0[tid];
        smem[SM_B1  + tid] = b1[tid];
        smem[SM_CB0 + tid] = cb0[tid];
        smem[SM_CB1 + tid] = cb1[tid];
    }

    const int warp = tid >> 5, lane = tid & 31;
    const int base = (blockIdx.x * WARPS + warp) * 32;
    float* __restrict__ par   = smem + SM_PAR  + warp * (32 * 16);
    float* __restrict__ sfeat = smem + SM_FEAT + warp * (32 * FSTR);

    int pi = -1;
    {
        const int idx = base + lane;
        float px = 2.0f, py = 2.0f, pz = 2.0f;
        if (idx < n) {
            const float4 ps = g_psort[idx];
            px = ps.x; py = ps.y; pz = ps.z;
            pi = __float_as_int(ps.w);
        }

        int s = 0; bool valid = false;
        #pragma unroll
        for (int k = SS - 1; k >= 0; k--) {
            const float lx = cBND[k*6+0], ly = cBND[k*6+1], lz = cBND[k*6+2];
            const float hx = cBND[k*6+3], hy = cBND[k*6+4], hz = cBND[k*6+5];
            const bool in = (px > lx) & (px < hx) & (py > ly) & (py < hy) & (pz > lz) & (pz < hz);
            if (in) { s = k; valid = true; }
        }
        const float m = valid ? 1.0f : 0.0f;

        const float bx0 = cBND[s*6+0], by0 = cBND[s*6+1], bz0 = cBND[s*6+2];
        const float bx1 = cBND[s*6+3], by1 = cBND[s*6+4], bz1 = cBND[s*6+5];
        const float pnx = (px - bx0) / (bx1 - bx0) * 2.0f - 1.0f;
        const float pny = (py - by0) / (by1 - by0) * 2.0f - 1.0f;
        const float pnz = (pz - bz0) / (bz1 - bz0) * 2.0f - 1.0f;

        const float us[3] = { pnx, pnx, pny };
        const float vs[3] = { pny, pnz, pnz };
        #pragma unroll
        for (int t = 0; t < 3; t++) {
            const float x = (us[t] + 1.0f) * 0.5f * (float)(RR - 1);
            const float y = (vs[t] + 1.0f) * 0.5f * (float)(RR - 1);
            const float xf = fminf(fmaxf(floorf(x), 0.0f), (float)(RR - 2));
            const float yf = fminf(fmaxf(floorf(y), 0.0f), (float)(RR - 2));
            const float wx = x - xf, wy = y - yf;
            float4 q;
            q.x = m * (1.0f - wx) * (1.0f - wy);
            q.y = m * wx * (1.0f - wy);
            q.z = m * (1.0f - wx) * wy;
            q.w = m * wx * wy;
            *(float4*)&par[lane * 16 + t * 4] = q;
            ((int*)par)[lane * 16 + 12 + t] = ((s * RR + (int)yf) * RR + (int)xf) * CC;
        }
    }
    __syncthreads();

    float c[2][4][4];

    // ================= SDF branch =================
    gather32(pxy, pxz, pyz, par, sfeat, lane);
    __syncwarp();
    gemm_layer(sfeat, smem + SM_W0, smem + SM_B0, c, lane);
    __syncwarp();
    relu_store_c(sfeat, c, lane);
    __syncwarp();
    gemm_layer(sfeat, smem + SM_W1, smem + SM_B1, c, lane);
    __syncwarp();
    relu_store_c(sfeat, c, lane);
    __syncwarp();

    float sdf;
    {
        const float* row = sfeat + lane * FSTR;
        float acc = cBO[0];
        #pragma unroll
        for (int j4 = 0; j4 < 8; j4++) {
            const float4 v = *(const float4*)&row[j4 * 4];
            acc += v.x * cWOUT[j4*4+0] + v.y * cWOUT[j4*4+1]
                 + v.z * cWOUT[j4*4+2] + v.w * cWOUT[j4*4+3];
        }
        sdf = tanhf(acc);
    }
    __syncwarp();

    // ================= Color branch =================
    gather32(cxy, cxz, cyz, par, sfeat, lane);
    __syncwarp();
    gemm_layer(sfeat, smem + SM_CW0, smem + SM_CB0, c, lane);
    __syncwarp();
    relu_store_c(sfeat, c, lane);
    __syncwarp();
    gemm_layer(sfeat, smem + SM_CW1, smem + SM_CB1, c, lane);
    __syncwarp();
    relu_store_c(sfeat, c, lane);
    __syncwarp();

    float rA = cCBO[0], gA = cCBO[1], bA = cCBO[2];
    {
        const float* row = sfeat + lane * FSTR;
        #pragma unroll
        for (int j = 0; j < HH; j++) {
            const float hv = row[j];
            rA += hv * cCWOUT[j*3 + 0];
            gA += hv * cCWOUT[j*3 + 1];
            bA += hv * cCWOUT[j*3 + 2];
        }
    }

    if (pi >= 0) {
        float4 o;
        o.x = 1.0f / (1.0f + expf(-rA));
        o.y = 1.0f / (1.0f + expf(-gA));
        o.z = 1.0f / (1.0f + expf(-bA));
        o.w = sdf;
        ((float4*)out)[pi] = o;
    }
}

extern "C" void kernel_launch(void* const* d_in, const int* in_sizes, int n_in,
                              void* d_out, int out_size) {
    const float* p          = (const float*)d_in[0];
    const float* boundaries = (const float*)d_in[1];
    const float* pxy        = (const float*)d_in[2];
    const float* pxz        = (const float*)d_in[3];
    const float* pyz        = (const float*)d_in[4];
    const float* cxy        = (const float*)d_in[5];
    const float* cxz        = (const float*)d_in[6];
    const float* cyz        = (const float*)d_in[7];
    const float* w0         = (const float*)d_in[8];
    const float* b0         = (const float*)d_in[9];
    const float* w1         = (const float*)d_in[10];
    const float* b1         = (const float*)d_in[11];
    const float* cw0        = (const float*)d_in[14];
    const float* cb0        = (const float*)d_in[15];
    const float* cw1        = (const float*)d_in[16];
    const float* cb1        = (const float*)d_in[17];

    cudaMemcpyToSymbolAsync(cWOUT,  d_in[12], HH*4,   0, cudaMemcpyDeviceToDevice, 0);
    cudaMemcpyToSymbolAsync(cBO,    d_in[13], 4,      0, cudaMemcpyDeviceToDevice, 0);
    cudaMemcpyToSymbolAsync(cCWOUT, d_in[18], HH*3*4, 0, cudaMemcpyDeviceToDevice, 0);
    cudaMemcpyToSymbolAsync(cCBO,   d_in[19], 3*4,    0, cudaMemcpyDeviceToDevice, 0);
    cudaMemcpyToSymbolAsync(cBND,   boundaries, SS*6*4, 0, cudaMemcpyDeviceToDevice, 0);

    const int n = in_sizes[0] / 3;
    float* out = (float*)d_out;

    // ---- spatial sort (x-major bins; scatter self-cleans bins for next replay) ----
    hist_kernel<<<(n + 255) / 256, 256>>>(p, n);
    scan_a_kernel<<<SCAN_BLKS, 1024>>>();
    scan_b_kernel<<<1, SCAN_BLKS>>>();
    scatter_kernel<<<(n + 255) / 256, 256>>>(p, n);

    const int smem_bytes = SMEM_FLOATS * (int)sizeof(float);
    cudaFuncSetAttribute(decoders_kernel,
                         cudaFuncAttributeMaxDynamicSharedMemorySize, smem_bytes);

    const int pts_per_block = NT;   // 256
    const int blocks = (n + pts_per_block - 1) / pts_per_block;
    decoders_kernel<<<blocks, NT, smem_bytes>>>(
        pxy, pxz, pyz, cxy, cxz, cyz,
        w0, w1, cw0, cw1, b0, b1, cb0, cb1, out, n);
}